// round 2
// baseline (speedup 1.0000x reference)
#include <cuda_runtime.h>
#include <cuda_bf16.h>

// out[i,c] = sum_k (neigh[i,k]>=0 ? data[neigh[i,k],c] : 0) * w[k,c]
// N=200000, K=27, C=64.
// 16 threads per point, float4 per thread (4 channels). 256 threads/block = 16 points.

#define KK 27
#define CV 16          // C/4 float4 per row
#define PTS 16         // points per block
#define THREADS 256

__global__ __launch_bounds__(THREADS)
void octree_dwconv_kernel(const float4* __restrict__ data,    // [N][16] float4
                          const float*  __restrict__ weights, // [27*64]
                          const int*    __restrict__ neigh,   // [N][27]
                          float4*       __restrict__ out)     // [N][16]
{
    __shared__ float4 s_w[KK * CV];   // 27*16 float4 = 6912 B
    __shared__ int    s_n[PTS * KK];  // 16*27 = 432 ints

    const int tid = threadIdx.x;
    const int base = blockIdx.x * PTS;

    // Stage weights (432 float4)
    const float4* w4 = reinterpret_cast<const float4*>(weights);
    #pragma unroll
    for (int i = tid; i < KK * CV; i += THREADS)
        s_w[i] = w4[i];

    // Stage ALL 432 neighbor indices (fix: loop, not single guarded load)
    #pragma unroll
    for (int i = tid; i < PTS * KK; i += THREADS)
        s_n[i] = neigh[base * KK + i];

    __syncthreads();

    const int p    = tid >> 4;   // point within block: 0..15
    const int lane = tid & 15;   // float4 column: 0..15
    const int i    = base + p;

    float4 acc = make_float4(0.f, 0.f, 0.f, 0.f);

    #pragma unroll
    for (int k = 0; k < KK; k++) {
        const int idx = s_n[p * KK + k];
        if (idx >= 0) {
            const float4 d  = __ldg(&data[(long long)idx * CV + lane]);
            const float4 wv = s_w[k * CV + lane];
            acc.x = fmaf(d.x, wv.x, acc.x);
            acc.y = fmaf(d.y, wv.y, acc.y);
            acc.z = fmaf(d.z, wv.z, acc.z);
            acc.w = fmaf(d.w, wv.w, acc.w);
        }
    }

    out[(long long)i * CV + lane] = acc;
}

extern "C" void kernel_launch(void* const* d_in, const int* in_sizes, int n_in,
                              void* d_out, int out_size) {
    const float4* data    = (const float4*)d_in[0];   // [N,64] fp32
    const float*  weights = (const float*)d_in[1];    // [27,1,64] fp32
    const int*    neigh   = (const int*)d_in[2];      // [N,27] int32
    float4* out = (float4*)d_out;

    const int N = in_sizes[0] / 64;                   // 200000
    const int grid = (N + PTS - 1) / PTS;             // 12500

    octree_dwconv_kernel<<<grid, THREADS>>>(data, weights, neigh, out);
}